// round 1
// baseline (speedup 1.0000x reference)
#include <cuda_runtime.h>
#include <math.h>

#define Bq   4
#define Nq   200000
#define Eq   128
#define IDXq 2048
#define TOT  (Bq * Nq)        // 800000 tokens
#define SEGS (Bq * IDXq)      // 8192 segments
#define OUTF (SEGS * Eq)      // 1048576 floats in `out` region

// Scratch (no cudaMalloc allowed)
__device__ float g_scores[TOT];
__device__ float g_e[TOT];
__device__ float g_segmax[SEGS];
__device__ float g_segsum[SEGS];

__device__ __forceinline__ void atomicMaxFloat(float* addr, float value) {
    // positive: signed-int max; negative: unsigned min (float order reversed in uint space)
    if (value >= 0.0f) atomicMax((int*)addr, __float_as_int(value));
    else               atomicMin((unsigned int*)addr, __float_as_uint(value));
}

// ---------------------------------------------------------------------------
// Init: zero `out` region of d_out, init segment max/sum. Runs every launch
// (graph replays), keeping kernel_launch idempotent.
// ---------------------------------------------------------------------------
__global__ void init_kernel(float* __restrict__ out) {
    int i = blockIdx.x * blockDim.x + threadIdx.x;
    if (i < OUTF) out[i] = 0.0f;
    if (i < SEGS) {
        g_segmax[i] = __int_as_float(0xFF800000); // -inf
        g_segsum[i] = 0.0f;
    }
}

// ---------------------------------------------------------------------------
// Pass 1: score[t] = ctx . tanh(W x_t + b) / sqrt(E), masked; atomicMax per seg.
// W^T staged in 64KB smem; each warp handles 8 tokens; x broadcast via shfl.
// Lane owns f = lane*4 .. lane*4+3 (float4 smem reads, conflict-free).
// ---------------------------------------------------------------------------
__global__ void __launch_bounds__(256) score_kernel(
    const float* __restrict__ x, const float* __restrict__ W,
    const float* __restrict__ bias, const float* __restrict__ ctx,
    const int* __restrict__ mask, const int* __restrict__ index)
{
    extern __shared__ float sW[]; // sW[e*128 + f] = W[f*128 + e]
    const int tid = threadIdx.x;
    for (int i = tid; i < Eq * Eq; i += blockDim.x) {
        int f = i >> 7, e = i & 127;
        sW[e * Eq + f] = W[i];
    }
    __syncthreads();

    const int lane = tid & 31;
    const int warp = tid >> 5;
    const int base = (blockIdx.x * 8 + warp) * 8; // 8 tokens per warp; grid exact

    float bl[4], cl[4];
#pragma unroll
    for (int j = 0; j < 4; j++) {
        bl[j] = __ldg(&bias[lane * 4 + j]);
        cl[j] = __ldg(&ctx[lane * 4 + j]);
    }

    float acc[8][4];
    float xr[8][4]; // xr[t][c] = x[token_t][c*32 + lane]
#pragma unroll
    for (int t = 0; t < 8; t++) {
        const float* xrow = x + (size_t)(base + t) * Eq;
#pragma unroll
        for (int c = 0; c < 4; c++) xr[t][c] = xrow[c * 32 + lane];
#pragma unroll
        for (int j = 0; j < 4; j++) acc[t][j] = bl[j];
    }

#pragma unroll
    for (int c = 0; c < 4; c++) {
#pragma unroll 4
        for (int k = 0; k < 32; k++) {
            const float4 w4 = *reinterpret_cast<const float4*>(&sW[(c * 32 + k) * Eq + lane * 4]);
#pragma unroll
            for (int t = 0; t < 8; t++) {
                const float xe = __shfl_sync(0xffffffffu, xr[t][c], k);
                acc[t][0] = fmaf(xe, w4.x, acc[t][0]);
                acc[t][1] = fmaf(xe, w4.y, acc[t][1]);
                acc[t][2] = fmaf(xe, w4.z, acc[t][2]);
                acc[t][3] = fmaf(xe, w4.w, acc[t][3]);
            }
        }
    }

#pragma unroll
    for (int t = 0; t < 8; t++) {
        const int tok = base + t;
        float s = tanhf(acc[t][0]) * cl[0] + tanhf(acc[t][1]) * cl[1]
                + tanhf(acc[t][2]) * cl[2] + tanhf(acc[t][3]) * cl[3];
#pragma unroll
        for (int o = 16; o > 0; o >>= 1) s += __shfl_xor_sync(0xffffffffu, s, o);
        if (lane == 0) {
            s *= 0.0883883476483184f; // 1/sqrt(128)
            if (mask[tok] == 0) s = -1e9f;
            g_scores[tok] = s;
            const int b = tok / Nq;
            atomicMaxFloat(&g_segmax[b * IDXq + index[tok]], s);
        }
    }
}

// ---------------------------------------------------------------------------
// Pass 2: e = exp(score - segmax); segsum += e.
// ---------------------------------------------------------------------------
__global__ void exp_kernel(const int* __restrict__ index) {
    const int t = blockIdx.x * blockDim.x + threadIdx.x; // grid exact: TOT
    const int b = t / Nq;
    const int seg = b * IDXq + index[t];
    const float e = expf(g_scores[t] - g_segmax[seg]);
    g_e[t] = e;
    atomicAdd(&g_segsum[seg], e);
}

// ---------------------------------------------------------------------------
// Pass 3: w = e/segsum; attn[t] = w; out[seg] += x_t * w (red.v4 scatter).
// One warp per token: lane covers 4 floats via float4.
// ---------------------------------------------------------------------------
__global__ void __launch_bounds__(256) scatter_kernel(
    const float* __restrict__ x, const int* __restrict__ index,
    float* __restrict__ out, float* __restrict__ attn)
{
    const int t = (blockIdx.x * blockDim.x + threadIdx.x) >> 5; // grid exact: TOT warps
    const int lane = threadIdx.x & 31;
    const int b = t / Nq;
    const int seg = b * IDXq + index[t];
    const float w = g_e[t] / g_segsum[seg];
    if (lane == 0) attn[t] = w;

    float4 v = reinterpret_cast<const float4*>(x + (size_t)t * Eq)[lane];
    v.x *= w; v.y *= w; v.z *= w; v.w *= w;
    float* dst = out + (size_t)seg * Eq + lane * 4;
    asm volatile("red.global.add.v4.f32 [%0], {%1, %2, %3, %4};"
                 :: "l"(dst), "f"(v.x), "f"(v.y), "f"(v.z), "f"(v.w)
                 : "memory");
}

// ---------------------------------------------------------------------------
extern "C" void kernel_launch(void* const* d_in, const int* in_sizes, int n_in,
                              void* d_out, int out_size)
{
    const float* x     = (const float*)d_in[0];
    const float* W     = (const float*)d_in[1];
    const float* bias  = (const float*)d_in[2];
    const float* ctx   = (const float*)d_in[3];
    const int*   mask  = (const int*)d_in[4];
    const int*   index = (const int*)d_in[5];

    float* out  = (float*)d_out;        // [B, IDX, E]
    float* attn = out + OUTF;           // [B, N]

    cudaFuncSetAttribute(score_kernel, cudaFuncAttributeMaxDynamicSharedMemorySize, 65536);

    init_kernel<<<(OUTF + 255) / 256, 256>>>(out);
    score_kernel<<<TOT / 64, 256, 65536>>>(x, W, bias, ctx, mask, index);
    exp_kernel<<<TOT / 256, 256>>>(index);
    scatter_kernel<<<TOT / 8, 256>>>(x, index, out, attn);
}

// round 4
// speedup vs baseline: 2.4271x; 2.4271x over previous
#include <cuda_runtime.h>
#include <cuda_bf16.h>
#include <math.h>
#include <stdint.h>

#define Bq   4
#define Nq   200000
#define Eq   128
#define IDXq 2048
#define TOT  (Bq * Nq)        // 800000 tokens
#define SEGS (Bq * IDXq)      // 8192 segments
#define OUTF (SEGS * Eq)      // 1048576 floats in `out` region
#define TM   256              // tokens per tile
#define TILES (TOT / TM)      // 3125 tiles
#define ROWB 272              // padded smem row stride in bytes (128 bf16 + 8 pad)

// ---------------- device scratch (no cudaMalloc allowed) -------------------
__device__ float g_scores[TOT];
__device__ float g_e[TOT];
__device__ float g_segmax[SEGS];
__device__ float g_segsum[SEGS];
__device__ __nv_bfloat16 g_Whi[Eq * Eq];
__device__ __nv_bfloat16 g_Wlo[Eq * Eq];

// ---------------- helpers ---------------------------------------------------
__device__ __forceinline__ uint32_t smem_u32(const void* p) {
    uint32_t a;
    asm("{ .reg .u64 t; cvta.to.shared.u64 t, %1; cvt.u32.u64 %0, t; }" : "=r"(a) : "l"(p));
    return a;
}
// pack two floats -> bf16x2 (lo = a, hi = b)
__device__ __forceinline__ uint32_t pack_bf16x2(float a, float b) {
    uint32_t r;
    asm("cvt.rn.bf16x2.f32 %0, %1, %2;" : "=r"(r) : "f"(b), "f"(a));
    return r;
}
__device__ __forceinline__ void ldsm_x4(uint32_t addr, uint32_t& r0, uint32_t& r1,
                                        uint32_t& r2, uint32_t& r3) {
    asm volatile("ldmatrix.sync.aligned.m8n8.x4.shared.b16 {%0,%1,%2,%3}, [%4];"
                 : "=r"(r0), "=r"(r1), "=r"(r2), "=r"(r3) : "r"(addr));
}
__device__ __forceinline__ void mma_bf16(float* d, uint32_t a0, uint32_t a1, uint32_t a2,
                                         uint32_t a3, uint32_t b0, uint32_t b1) {
    asm volatile(
        "mma.sync.aligned.m16n8k16.row.col.f32.bf16.bf16.f32 "
        "{%0,%1,%2,%3}, {%4,%5,%6,%7}, {%8,%9}, {%0,%1,%2,%3};"
        : "+f"(d[0]), "+f"(d[1]), "+f"(d[2]), "+f"(d[3])
        : "r"(a0), "r"(a1), "r"(a2), "r"(a3), "r"(b0), "r"(b1));
}
__device__ __forceinline__ void atomicMaxFloat(float* addr, float value) {
    if (value >= 0.0f) atomicMax((int*)addr, __float_as_int(value));
    else               atomicMin((unsigned int*)addr, __float_as_uint(value));
}

// ---------------------------------------------------------------------------
// W split prep: W -> bf16 hi + bf16 lo (residual)
// ---------------------------------------------------------------------------
__global__ void wprep_kernel(const float* __restrict__ W) {
    int i = blockIdx.x * blockDim.x + threadIdx.x; // 16384 exact
    float w = W[i];
    __nv_bfloat16 hi = __float2bfloat16_rn(w);
    g_Whi[i] = hi;
    g_Wlo[i] = __float2bfloat16_rn(w - __bfloat162float(hi));
}

// ---------------------------------------------------------------------------
// Init: zero `out`, init segmax/segsum (idempotent across graph replays)
// ---------------------------------------------------------------------------
__global__ void init_kernel(float* __restrict__ out) {
    int i = blockIdx.x * blockDim.x + threadIdx.x;
    if (i < OUTF) out[i] = 0.0f;
    if (i < SEGS) {
        g_segmax[i] = __int_as_float(0xFF800000); // -inf
        g_segsum[i] = 0.0f;
    }
}

// ---------------------------------------------------------------------------
// Score pass: persistent HMMA (mma.sync bf16x3-split) GEMM + tanh/ctx epilogue.
// tile: 256 tokens x 128 features, K = 128. 16 warps x 16 rows.
// SMEM: bias 512 | ctx 512 | Wh 34816 | Wl 34816 | Xh 69632 | Xl 69632
// ---------------------------------------------------------------------------
#define SM_B   0
#define SM_C   512
#define SM_WH  1024
#define SM_WL  (SM_WH + 128 * ROWB)   // 35840
#define SM_XH  (SM_WL + 128 * ROWB)   // 70656
#define SM_XL  (SM_XH + 256 * ROWB)   // 140288
#define SM_TOTAL (SM_XL + 256 * ROWB) // 209920

__global__ void __launch_bounds__(512, 1) score_kernel(
    const float* __restrict__ x, const float* __restrict__ bias,
    const float* __restrict__ ctx, const int* __restrict__ mask,
    const int* __restrict__ index)
{
    extern __shared__ char smem[];
    const uint32_t sb = smem_u32(smem);
    const int tid  = threadIdx.x;
    const int wid  = tid >> 5;
    const int lane = tid & 31;

    float* bS = reinterpret_cast<float*>(smem + SM_B);
    float* cS = reinterpret_cast<float*>(smem + SM_C);
    if (tid < 128) { bS[tid] = bias[tid]; cS[tid] = ctx[tid]; }

    // stage W hi/lo into padded smem (row f, stride 272B). 512 thr, 128 rows.
    {
        const int r = tid >> 2;
        const int c0 = (tid & 3) * 32;
#pragma unroll
        for (int i = 0; i < 4; i++) {
            const int c = c0 + i * 8;
            *reinterpret_cast<uint4*>(smem + SM_WH + r * ROWB + c * 2) =
                *reinterpret_cast<const uint4*>(&g_Whi[r * Eq + c]);
            *reinterpret_cast<uint4*>(smem + SM_WL + r * ROWB + c * 2) =
                *reinterpret_cast<const uint4*>(&g_Wlo[r * Eq + c]);
        }
    }
    __syncthreads();

    // per-warp ldmatrix source addresses
    const int m0 = wid * 16;
    const int aRow = m0 + (lane & 15);
    const uint32_t aColB = (lane >> 4) * 16;            // bytes: 8 bf16
    const uint32_t aAddrH = sb + SM_XH + (uint32_t)aRow * ROWB + aColB;
    const uint32_t aAddrL = aAddrH + (SM_XL - SM_XH);
    const int rowB = (lane & 7) + ((lane & 16) >> 1);   // 0..15
    const uint32_t colB = (lane & 8) ? 16u : 0u;        // bytes: k 0-7 vs 8-15
    const uint32_t bBaseH = sb + SM_WH + (uint32_t)rowB * ROWB + colB;
    const uint32_t bBaseL = bBaseH + (SM_WL - SM_WH);

    for (int tile = blockIdx.x; tile < TILES; tile += gridDim.x) {
        const int tbase = tile * TM;

        // ---- load + split x tile into smem hi/lo ----
        {
            const int r = tid >> 1;
            const int half = (tid & 1) * 64;
            const float* xrow = x + (size_t)(tbase + r) * Eq;
#pragma unroll
            for (int i = 0; i < 8; i++) {
                const int c = half + i * 8;
                float4 f0 = *reinterpret_cast<const float4*>(xrow + c);
                float4 f1 = *reinterpret_cast<const float4*>(xrow + c + 4);
                float fv[8] = {f0.x, f0.y, f0.z, f0.w, f1.x, f1.y, f1.z, f1.w};
                float hv[8], lv[8];
#pragma unroll
                for (int j = 0; j < 8; j++) {
                    hv[j] = __bfloat162float(__float2bfloat16_rn(fv[j]));
                    lv[j] = fv[j] - hv[j];
                }
                uint4 uh, ul;
                uh.x = pack_bf16x2(hv[0], hv[1]); uh.y = pack_bf16x2(hv[2], hv[3]);
                uh.z = pack_bf16x2(hv[4], hv[5]); uh.w = pack_bf16x2(hv[6], hv[7]);
                ul.x = pack_bf16x2(lv[0], lv[1]); ul.y = pack_bf16x2(lv[2], lv[3]);
                ul.z = pack_bf16x2(lv[4], lv[5]); ul.w = pack_bf16x2(lv[6], lv[7]);
                *reinterpret_cast<uint4*>(smem + SM_XH + r * ROWB + c * 2) = uh;
                *reinterpret_cast<uint4*>(smem + SM_XL + r * ROWB + c * 2) = ul;
            }
        }
        __syncthreads();

        // ---- MMA mainloop: d = xh*Wh + xh*Wl + xl*Wh ----
        float d[16][4];
#pragma unroll
        for (int nb = 0; nb < 16; nb++)
#pragma unroll
            for (int j = 0; j < 4; j++) d[nb][j] = 0.0f;

#pragma unroll
        for (int k = 0; k < 8; k++) {
            uint32_t ah0, ah1, ah2, ah3, al0, al1, al2, al3;
            ldsm_x4(aAddrH + k * 32, ah0, ah1, ah2, ah3);
            ldsm_x4(aAddrL + k * 32, al0, al1, al2, al3);
#pragma unroll
            for (int np = 0; np < 8; np++) {
                uint32_t bh0, bh1, bh2, bh3, bl0, bl1, bl2, bl3;
                const uint32_t boff = (uint32_t)np * (16 * ROWB) + k * 32;
                ldsm_x4(bBaseH + boff, bh0, bh1, bh2, bh3);
                ldsm_x4(bBaseL + boff, bl0, bl1, bl2, bl3);
                mma_bf16(d[np * 2],     ah0, ah1, ah2, ah3, bh0, bh1);
                mma_bf16(d[np * 2],     ah0, ah1, ah2, ah3, bl0, bl1);
                mma_bf16(d[np * 2],     al0, al1, al2, al3, bh0, bh1);
                mma_bf16(d[np * 2 + 1], ah0, ah1, ah2, ah3, bh2, bh3);
                mma_bf16(d[np * 2 + 1], ah0, ah1, ah2, ah3, bl2, bl3);
                mma_bf16(d[np * 2 + 1], al0, al1, al2, al3, bh2, bh3);
            }
        }

        // ---- epilogue: score = ctx . tanh(z + b) / sqrt(E) ----
        float p0 = 0.0f, p1 = 0.0f;
#pragma unroll
        for (int nb = 0; nb < 16; nb++) {
            const int n0 = nb * 8 + (lane & 3) * 2;
            const float2 bb = *reinterpret_cast<const float2*>(&bS[n0]);
            const float2 cc = *reinterpret_cast<const float2*>(&cS[n0]);
            p0 = fmaf(tanhf(d[nb][0] + bb.x), cc.x, p0);
            p0 = fmaf(tanhf(d[nb][1] + bb.y), cc.y, p0);
            p1 = fmaf(tanhf(d[nb][2] + bb.x), cc.x, p1);
            p1 = fmaf(tanhf(d[nb][3] + bb.y), cc.y, p1);
        }
        p0 += __shfl_xor_sync(0xffffffffu, p0, 1);
        p0 += __shfl_xor_sync(0xffffffffu, p0, 2);
        p1 += __shfl_xor_sync(0xffffffffu, p1, 1);
        p1 += __shfl_xor_sync(0xffffffffu, p1, 2);

        if ((lane & 3) == 0) {
            const int q = lane >> 2;
            {
                const int tok = tbase + m0 + q;
                float s = p0 * 0.08838834764831845f;
                if (mask[tok] == 0) s = -1e9f;
                g_scores[tok] = s;
                const int b = tok / Nq;
                atomicMaxFloat(&g_segmax[b * IDXq + index[tok]], s);
            }
            {
                const int tok = tbase + m0 + q + 8;
                float s = p1 * 0.08838834764831845f;
                if (mask[tok] == 0) s = -1e9f;
                g_scores[tok] = s;
                const int b = tok / Nq;
                atomicMaxFloat(&g_segmax[b * IDXq + index[tok]], s);
            }
        }
        __syncthreads(); // all warps done reading x smem before next tile store
    }
}

// ---------------------------------------------------------------------------
// Pass 2: e = exp(score - segmax); segsum += e.
// ---------------------------------------------------------------------------
__global__ void exp_kernel(const int* __restrict__ index) {
    const int t = blockIdx.x * blockDim.x + threadIdx.x; // grid exact: TOT
    const int b = t / Nq;
    const int seg = b * IDXq + index[t];
    const float e = expf(g_scores[t] - g_segmax[seg]);
    g_e[t] = e;
    atomicAdd(&g_segsum[seg], e);
}

// ---------------------------------------------------------------------------
// Pass 3: w = e/segsum; attn[t] = w; out[seg] += x_t * w (red.v4 scatter).
// ---------------------------------------------------------------------------
__global__ void __launch_bounds__(256) scatter_kernel(
    const float* __restrict__ x, const int* __restrict__ index,
    float* __restrict__ out, float* __restrict__ attn)
{
    const int t = (blockIdx.x * blockDim.x + threadIdx.x) >> 5; // grid exact: TOT warps
    const int lane = threadIdx.x & 31;
    const int b = t / Nq;
    const int seg = b * IDXq + index[t];
    const float w = g_e[t] / g_segsum[seg];
    if (lane == 0) attn[t] = w;

    float4 v = reinterpret_cast<const float4*>(x + (size_t)t * Eq)[lane];
    v.x *= w; v.y *= w; v.z *= w; v.w *= w;
    float* dst = out + (size_t)seg * Eq + lane * 4;
    asm volatile("red.global.add.v4.f32 [%0], {%1, %2, %3, %4};"
                 :: "l"(dst), "f"(v.x), "f"(v.y), "f"(v.z), "f"(v.w)
                 : "memory");
}

// ---------------------------------------------------------------------------
extern "C" void kernel_launch(void* const* d_in, const int* in_sizes, int n_in,
                              void* d_out, int out_size)
{
    const float* x     = (const float*)d_in[0];
    const float* W     = (const float*)d_in[1];
    const float* bias  = (const float*)d_in[2];
    const float* ctx   = (const float*)d_in[3];
    const int*   mask  = (const int*)d_in[4];
    const int*   index = (const int*)d_in[5];

    float* out  = (float*)d_out;        // [B, IDX, E]
    float* attn = out + OUTF;           // [B, N]

    cudaFuncSetAttribute(score_kernel, cudaFuncAttributeMaxDynamicSharedMemorySize, SM_TOTAL);

    wprep_kernel<<<Eq * Eq / 256, 256>>>(W);
    init_kernel<<<(OUTF + 255) / 256, 256>>>(out);
    score_kernel<<<152, 512, SM_TOTAL>>>(x, bias, ctx, mask, index);
    exp_kernel<<<TOT / 256, 256>>>(index);
    scatter_kernel<<<TOT / 8, 256>>>(x, index, out, attn);
}

// round 5
// speedup vs baseline: 3.0008x; 1.2364x over previous
#include <cuda_runtime.h>
#include <cuda_bf16.h>
#include <math.h>
#include <stdint.h>

#define Bq   4
#define Nq   200000
#define Eq   128
#define IDXq 2048
#define TOT  (Bq * Nq)        // 800000 tokens
#define SEGS (Bq * IDXq)      // 8192 segments
#define OUTF (SEGS * Eq)      // 1048576 floats in `out` region
#define TM   128              // tokens per tile
#define TILES (TOT / TM)      // 6250 tiles
#define ROWB 272              // padded smem row stride in bytes (128 bf16 + 8 pad)

// ---------------- device scratch (no cudaMalloc allowed) -------------------
__device__ float g_scores[TOT];
__device__ float g_e[TOT];
__device__ float g_segmax[SEGS];
__device__ float g_segsum[SEGS];
__device__ __nv_bfloat16 g_Whi[Eq * Eq];
__device__ __nv_bfloat16 g_Wlo[Eq * Eq];

// ---------------- helpers ---------------------------------------------------
__device__ __forceinline__ uint32_t smem_u32(const void* p) {
    uint32_t a;
    asm("{ .reg .u64 t; cvta.to.shared.u64 t, %1; cvt.u32.u64 %0, t; }" : "=r"(a) : "l"(p));
    return a;
}
__device__ __forceinline__ uint32_t pack_bf16x2(float a, float b) {
    uint32_t r;
    asm("cvt.rn.bf16x2.f32 %0, %1, %2;" : "=r"(r) : "f"(b), "f"(a));
    return r;
}
__device__ __forceinline__ void ldsm_x4(uint32_t addr, uint32_t& r0, uint32_t& r1,
                                        uint32_t& r2, uint32_t& r3) {
    asm volatile("ldmatrix.sync.aligned.m8n8.x4.shared.b16 {%0,%1,%2,%3}, [%4];"
                 : "=r"(r0), "=r"(r1), "=r"(r2), "=r"(r3) : "r"(addr));
}
__device__ __forceinline__ void mma_bf16(float* d, uint32_t a0, uint32_t a1, uint32_t a2,
                                         uint32_t a3, uint32_t b0, uint32_t b1) {
    asm volatile(
        "mma.sync.aligned.m16n8k16.row.col.f32.bf16.bf16.f32 "
        "{%0,%1,%2,%3}, {%4,%5,%6,%7}, {%8,%9}, {%0,%1,%2,%3};"
        : "+f"(d[0]), "+f"(d[1]), "+f"(d[2]), "+f"(d[3])
        : "r"(a0), "r"(a1), "r"(a2), "r"(a3), "r"(b0), "r"(b1));
}
// tanh(x) = 1 - 2/(exp(2x)+1), via ex2.approx + rcp.approx (~2^-21 max rel err)
__device__ __forceinline__ float fast_tanh(float x) {
    float e, r;
    asm("ex2.approx.f32 %0, %1;" : "=f"(e) : "f"(x * 2.8853900817779268f));
    asm("rcp.approx.f32 %0, %1;" : "=f"(r) : "f"(e + 1.0f));
    return fmaf(-2.0f, r, 1.0f);
}
__device__ __forceinline__ void atomicMaxFloat(float* addr, float value) {
    if (value >= 0.0f) atomicMax((int*)addr, __float_as_int(value));
    else               atomicMin((unsigned int*)addr, __float_as_uint(value));
}

// ---------------------------------------------------------------------------
__global__ void wprep_kernel(const float* __restrict__ W) {
    int i = blockIdx.x * blockDim.x + threadIdx.x; // 16384 exact
    float w = W[i];
    __nv_bfloat16 hi = __float2bfloat16_rn(w);
    g_Whi[i] = hi;
    g_Wlo[i] = __float2bfloat16_rn(w - __bfloat162float(hi));
}

__global__ void init_kernel(float* __restrict__ out) {
    int i = blockIdx.x * blockDim.x + threadIdx.x;
    if (i < OUTF / 4) reinterpret_cast<float4*>(out)[i] = make_float4(0.f, 0.f, 0.f, 0.f);
    if (i < SEGS) {
        g_segmax[i] = __int_as_float(0xFF800000); // -inf
        g_segsum[i] = 0.0f;
    }
}

// ---------------------------------------------------------------------------
// Score pass: persistent HMMA bf16x3-split GEMM, register-prefetch pipelined.
// tile: 128 tokens x 128 features, K=128. 8 warps x 16 rows.
// ---------------------------------------------------------------------------
#define SM_B   0
#define SM_C   512
#define SM_WH  1024
#define SM_WL  (SM_WH + 128 * ROWB)
#define SM_XH  (SM_WL + 128 * ROWB)
#define SM_XL  (SM_XH + 128 * ROWB)
#define SM_TOTAL (SM_XL + 128 * ROWB)  // 140288

__global__ void __launch_bounds__(256, 1) score_kernel(
    const float* __restrict__ x, const float* __restrict__ bias,
    const float* __restrict__ ctx, const int* __restrict__ mask,
    const int* __restrict__ index)
{
    extern __shared__ char smem[];
    const uint32_t sb = smem_u32(smem);
    const int tid  = threadIdx.x;
    const int wid  = tid >> 5;
    const int lane = tid & 31;

    float* bS = reinterpret_cast<float*>(smem + SM_B);
    float* cS = reinterpret_cast<float*>(smem + SM_C);
    if (tid < 128) { bS[tid] = bias[tid]; cS[tid] = ctx[tid]; }

    // stage W hi/lo (row f, stride 272B). 256 thr, 128 rows.
    {
        const int r = tid >> 1;
        const int c0 = (tid & 1) * 64;
#pragma unroll
        for (int i = 0; i < 8; i++) {
            const int c = c0 + i * 8;
            *reinterpret_cast<uint4*>(smem + SM_WH + r * ROWB + c * 2) =
                *reinterpret_cast<const uint4*>(&g_Whi[r * Eq + c]);
            *reinterpret_cast<uint4*>(smem + SM_WL + r * ROWB + c * 2) =
                *reinterpret_cast<const uint4*>(&g_Wlo[r * Eq + c]);
        }
    }

    // per-thread x-load geometry: row r = tid>>1, cols half..half+63
    const int xr   = tid >> 1;
    const int half = (tid & 1) * 64;

    // per-warp ldmatrix addresses
    const int m0 = wid * 16;
    const int aRow = m0 + (lane & 15);
    const uint32_t aColB = (lane >> 4) * 16;
    const uint32_t aAddrH = sb + SM_XH + (uint32_t)aRow * ROWB + aColB;
    const uint32_t aAddrL = aAddrH + (uint32_t)(SM_XL - SM_XH);
    const int rowB = (lane & 7) + ((lane & 16) >> 1);
    const uint32_t colB = (lane & 8) ? 16u : 0u;
    const uint32_t bBaseH = sb + SM_WH + (uint32_t)rowB * ROWB + colB;
    const uint32_t bBaseL = bBaseH + (uint32_t)(SM_WL - SM_WH);

    float4 st[16];   // staging: 64 floats for next tile

    // ---- prologue: load tile0 into regs ----
    int tile = blockIdx.x;
    {
        const float* xrow = x + (size_t)(tile * TM + xr) * Eq + half;
#pragma unroll
        for (int i = 0; i < 16; i++) st[i] = reinterpret_cast<const float4*>(xrow)[i];
    }
    __syncthreads(); // W staged
    // convert tile0 into smem
    {
#pragma unroll
        for (int i = 0; i < 8; i++) {
            float fv[8] = {st[2*i].x, st[2*i].y, st[2*i].z, st[2*i].w,
                           st[2*i+1].x, st[2*i+1].y, st[2*i+1].z, st[2*i+1].w};
            float hv[8], lv[8];
#pragma unroll
            for (int j = 0; j < 8; j++) {
                hv[j] = __bfloat162float(__float2bfloat16_rn(fv[j]));
                lv[j] = fv[j] - hv[j];
            }
            uint4 uh, ul;
            uh.x = pack_bf16x2(hv[0], hv[1]); uh.y = pack_bf16x2(hv[2], hv[3]);
            uh.z = pack_bf16x2(hv[4], hv[5]); uh.w = pack_bf16x2(hv[6], hv[7]);
            ul.x = pack_bf16x2(lv[0], lv[1]); ul.y = pack_bf16x2(lv[2], lv[3]);
            ul.z = pack_bf16x2(lv[4], lv[5]); ul.w = pack_bf16x2(lv[6], lv[7]);
            const int c = half + i * 8;
            *reinterpret_cast<uint4*>(smem + SM_XH + xr * ROWB + c * 2) = uh;
            *reinterpret_cast<uint4*>(smem + SM_XL + xr * ROWB + c * 2) = ul;
        }
    }
    __syncthreads();

    while (tile < TILES) {
        const int tbase = tile * TM;
        const int next  = tile + gridDim.x;

        // ---- issue prefetch loads for next tile (latency hidden by MMA) ----
        if (next < TILES) {
            const float* xrow = x + (size_t)(next * TM + xr) * Eq + half;
#pragma unroll
            for (int i = 0; i < 16; i++) st[i] = reinterpret_cast<const float4*>(xrow)[i];
        }

        // ---- MMA mainloop: d = xh*Wh + xh*Wl + xl*Wh ----
        float d[16][4];
#pragma unroll
        for (int nb = 0; nb < 16; nb++)
#pragma unroll
            for (int j = 0; j < 4; j++) d[nb][j] = 0.0f;

#pragma unroll
        for (int k = 0; k < 8; k++) {
            uint32_t ah0, ah1, ah2, ah3, al0, al1, al2, al3;
            ldsm_x4(aAddrH + k * 32, ah0, ah1, ah2, ah3);
            ldsm_x4(aAddrL + k * 32, al0, al1, al2, al3);
#pragma unroll
            for (int np = 0; np < 8; np++) {
                uint32_t bh0, bh1, bh2, bh3, bl0, bl1, bl2, bl3;
                const uint32_t boff = (uint32_t)np * (16 * ROWB) + k * 32;
                ldsm_x4(bBaseH + boff, bh0, bh1, bh2, bh3);
                ldsm_x4(bBaseL + boff, bl0, bl1, bl2, bl3);
                mma_bf16(d[np * 2],     ah0, ah1, ah2, ah3, bh0, bh1);
                mma_bf16(d[np * 2],     ah0, ah1, ah2, ah3, bl0, bl1);
                mma_bf16(d[np * 2],     al0, al1, al2, al3, bh0, bh1);
                mma_bf16(d[np * 2 + 1], ah0, ah1, ah2, ah3, bh2, bh3);
                mma_bf16(d[np * 2 + 1], ah0, ah1, ah2, ah3, bl2, bl3);
                mma_bf16(d[np * 2 + 1], al0, al1, al2, al3, bh2, bh3);
            }
        }

        // ---- epilogue: score = ctx . tanh(z + b) / sqrt(E) ----
        float p0 = 0.0f, p1 = 0.0f;
#pragma unroll
        for (int nb = 0; nb < 16; nb++) {
            const int n0 = nb * 8 + (lane & 3) * 2;
            const float2 bb = *reinterpret_cast<const float2*>(&bS[n0]);
            const float2 cc = *reinterpret_cast<const float2*>(&cS[n0]);
            p0 = fmaf(fast_tanh(d[nb][0] + bb.x), cc.x, p0);
            p0 = fmaf(fast_tanh(d[nb][1] + bb.y), cc.y, p0);
            p1 = fmaf(fast_tanh(d[nb][2] + bb.x), cc.x, p1);
            p1 = fmaf(fast_tanh(d[nb][3] + bb.y), cc.y, p1);
        }
        p0 += __shfl_xor_sync(0xffffffffu, p0, 1);
        p0 += __shfl_xor_sync(0xffffffffu, p0, 2);
        p1 += __shfl_xor_sync(0xffffffffu, p1, 1);
        p1 += __shfl_xor_sync(0xffffffffu, p1, 2);

        if ((lane & 3) == 0) {
            const int q = lane >> 2;
            {
                const int tok = tbase + m0 + q;
                float s = p0 * 0.08838834764831845f;
                if (mask[tok] == 0) s = -1e9f;
                g_scores[tok] = s;
                atomicMaxFloat(&g_segmax[(tok / Nq) * IDXq + index[tok]], s);
            }
            {
                const int tok = tbase + m0 + q + 8;
                float s = p1 * 0.08838834764831845f;
                if (mask[tok] == 0) s = -1e9f;
                g_scores[tok] = s;
                atomicMaxFloat(&g_segmax[(tok / Nq) * IDXq + index[tok]], s);
            }
        }
        __syncthreads(); // all warps finished reading smem x

        // ---- convert staged regs -> smem for next tile ----
        if (next < TILES) {
#pragma unroll
            for (int i = 0; i < 8; i++) {
                float fv[8] = {st[2*i].x, st[2*i].y, st[2*i].z, st[2*i].w,
                               st[2*i+1].x, st[2*i+1].y, st[2*i+1].z, st[2*i+1].w};
                float hv[8], lv[8];
#pragma unroll
                for (int j = 0; j < 8; j++) {
                    hv[j] = __bfloat162float(__float2bfloat16_rn(fv[j]));
                    lv[j] = fv[j] - hv[j];
                }
                uint4 uh, ul;
                uh.x = pack_bf16x2(hv[0], hv[1]); uh.y = pack_bf16x2(hv[2], hv[3]);
                uh.z = pack_bf16x2(hv[4], hv[5]); uh.w = pack_bf16x2(hv[6], hv[7]);
                ul.x = pack_bf16x2(lv[0], lv[1]); ul.y = pack_bf16x2(lv[2], lv[3]);
                ul.z = pack_bf16x2(lv[4], lv[5]); ul.w = pack_bf16x2(lv[6], lv[7]);
                const int c = half + i * 8;
                *reinterpret_cast<uint4*>(smem + SM_XH + xr * ROWB + c * 2) = uh;
                *reinterpret_cast<uint4*>(smem + SM_XL + xr * ROWB + c * 2) = ul;
            }
            __syncthreads();
        }
        tile = next;
    }
}

// ---------------------------------------------------------------------------
__global__ void exp_kernel(const int* __restrict__ index) {
    const int t = blockIdx.x * blockDim.x + threadIdx.x; // grid exact: TOT
    const int b = t / Nq;
    const int seg = b * IDXq + index[t];
    const float e = __expf(g_scores[t] - g_segmax[seg]);
    g_e[t] = e;
    atomicAdd(&g_segsum[seg], e);
}

// ---------------------------------------------------------------------------
__global__ void __launch_bounds__(256) scatter_kernel(
    const float* __restrict__ x, const int* __restrict__ index,
    float* __restrict__ out, float* __restrict__ attn)
{
    const int t = (blockIdx.x * blockDim.x + threadIdx.x) >> 5; // grid exact: TOT warps
    const int lane = threadIdx.x & 31;
    const int b = t / Nq;
    const int seg = b * IDXq + index[t];
    const float w = g_e[t] / g_segsum[seg];
    if (lane == 0) attn[t] = w;

    float4 v = reinterpret_cast<const float4*>(x + (size_t)t * Eq)[lane];
    v.x *= w; v.y *= w; v.z *= w; v.w *= w;
    float* dst = out + (size_t)seg * Eq + lane * 4;
    asm volatile("red.global.add.v4.f32 [%0], {%1, %2, %3, %4};"
                 :: "l"(dst), "f"(v.x), "f"(v.y), "f"(v.z), "f"(v.w)
                 : "memory");
}

// ---------------------------------------------------------------------------
extern "C" void kernel_launch(void* const* d_in, const int* in_sizes, int n_in,
                              void* d_out, int out_size)
{
    const float* x     = (const float*)d_in[0];
    const float* W     = (const float*)d_in[1];
    const float* bias  = (const float*)d_in[2];
    const float* ctx   = (const float*)d_in[3];
    const int*   mask  = (const int*)d_in[4];
    const int*   index = (const int*)d_in[5];

    float* out  = (float*)d_out;        // [B, IDX, E]
    float* attn = out + OUTF;           // [B, N]

    cudaFuncSetAttribute(score_kernel, cudaFuncAttributeMaxDynamicSharedMemorySize, SM_TOTAL);

    wprep_kernel<<<Eq * Eq / 256, 256>>>(W);
    init_kernel<<<(OUTF / 4 + 255) / 256, 256>>>(out);
    score_kernel<<<152, 256, SM_TOTAL>>>(x, bias, ctx, mask, index);
    exp_kernel<<<TOT / 256, 256>>>(index);
    scatter_kernel<<<TOT / 8, 256>>>(x, index, out, attn);
}

// round 6
// speedup vs baseline: 3.0415x; 1.0135x over previous
#include <cuda_runtime.h>
#include <cuda_bf16.h>
#include <math.h>
#include <stdint.h>

#define Bq   4
#define Nq   200000
#define Eq   128
#define IDXq 2048
#define TOT  (Bq * Nq)        // 800000 tokens
#define SEGS (Bq * IDXq)      // 8192 segments
#define OUTF (SEGS * Eq)      // 1048576 floats in `out` region
#define TM   128              // tokens per tile
#define TILES (TOT / TM)      // 6250 tiles
#define ROWB 272              // padded smem row stride in bytes (128 bf16 + 8 pad)
#define NREP 4                // scatter atomic replicas

// ---------------- device scratch (no cudaMalloc allowed) -------------------
__device__ float g_scores[TOT];
__device__ float g_e[TOT];
__device__ float g_segmax[SEGS];
__device__ float g_segsum[SEGS];
__device__ __nv_bfloat16 g_Whi[Eq * Eq];
__device__ __nv_bfloat16 g_Wlo[Eq * Eq];
__device__ float g_part[NREP * OUTF];   // 16MB scatter replicas (L2-resident)

// ---------------- helpers ---------------------------------------------------
__device__ __forceinline__ uint32_t smem_u32(const void* p) {
    uint32_t a;
    asm("{ .reg .u64 t; cvta.to.shared.u64 t, %1; cvt.u32.u64 %0, t; }" : "=r"(a) : "l"(p));
    return a;
}
__device__ __forceinline__ uint32_t pack_bf16x2(float a, float b) {
    uint32_t r;
    asm("cvt.rn.bf16x2.f32 %0, %1, %2;" : "=r"(r) : "f"(b), "f"(a));
    return r;
}
__device__ __forceinline__ void ldsm_x4(uint32_t addr, uint32_t& r0, uint32_t& r1,
                                        uint32_t& r2, uint32_t& r3) {
    asm volatile("ldmatrix.sync.aligned.m8n8.x4.shared.b16 {%0,%1,%2,%3}, [%4];"
                 : "=r"(r0), "=r"(r1), "=r"(r2), "=r"(r3) : "r"(addr));
}
__device__ __forceinline__ void mma_bf16(float* d, uint32_t a0, uint32_t a1, uint32_t a2,
                                         uint32_t a3, uint32_t b0, uint32_t b1) {
    asm volatile(
        "mma.sync.aligned.m16n8k16.row.col.f32.bf16.bf16.f32 "
        "{%0,%1,%2,%3}, {%4,%5,%6,%7}, {%8,%9}, {%0,%1,%2,%3};"
        : "+f"(d[0]), "+f"(d[1]), "+f"(d[2]), "+f"(d[3])
        : "r"(a0), "r"(a1), "r"(a2), "r"(a3), "r"(b0), "r"(b1));
}
// tanh(x) = 1 - 2/(exp(2x)+1), via ex2.approx + rcp.approx (~2^-21 max rel err)
__device__ __forceinline__ float fast_tanh(float x) {
    float e, r;
    asm("ex2.approx.f32 %0, %1;" : "=f"(e) : "f"(x * 2.8853900817779268f));
    asm("rcp.approx.f32 %0, %1;" : "=f"(r) : "f"(e + 1.0f));
    return fmaf(-2.0f, r, 1.0f);
}
__device__ __forceinline__ void atomicMaxFloat(float* addr, float value) {
    if (value >= 0.0f) atomicMax((int*)addr, __float_as_int(value));
    else               atomicMin((unsigned int*)addr, __float_as_uint(value));
}

// ---------------------------------------------------------------------------
__global__ void wprep_kernel(const float* __restrict__ W) {
    int i = blockIdx.x * blockDim.x + threadIdx.x; // 16384 exact
    float w = W[i];
    __nv_bfloat16 hi = __float2bfloat16_rn(w);
    g_Whi[i] = hi;
    g_Wlo[i] = __float2bfloat16_rn(w - __bfloat162float(hi));
}

// zero replicas + init segment stats (idempotent across graph replays)
__global__ void init_kernel() {
    int i = blockIdx.x * blockDim.x + threadIdx.x;   // grid covers NREP*OUTF/4
    reinterpret_cast<float4*>(g_part)[i] = make_float4(0.f, 0.f, 0.f, 0.f);
    if (i < SEGS) {
        g_segmax[i] = __int_as_float(0xFF800000); // -inf
        g_segsum[i] = 0.0f;
    }
}

// ---------------------------------------------------------------------------
// Score pass: persistent HMMA bf16x3-split GEMM, register-prefetch pipelined.
// tile: 128 tokens x 128 features, K=128. 8 warps in 4x2 (rows32 x cols64).
// ---------------------------------------------------------------------------
#define SM_B   0
#define SM_C   512
#define SM_P   1024                    // partial[128][2] floats
#define SM_WH  2048
#define SM_WL  (SM_WH + 128 * ROWB)
#define SM_XH  (SM_WL + 128 * ROWB)
#define SM_XL  (SM_XH + 128 * ROWB)
#define SM_TOTAL (SM_XL + 128 * ROWB)  // 141312

__global__ void __launch_bounds__(256, 1) score_kernel(
    const float* __restrict__ x, const float* __restrict__ bias,
    const float* __restrict__ ctx, const int* __restrict__ mask,
    const int* __restrict__ index)
{
    extern __shared__ char smem[];
    const uint32_t sb = smem_u32(smem);
    const int tid  = threadIdx.x;
    const int wid  = tid >> 5;
    const int lane = tid & 31;

    float* bS = reinterpret_cast<float*>(smem + SM_B);
    float* cS = reinterpret_cast<float*>(smem + SM_C);
    float* pS = reinterpret_cast<float*>(smem + SM_P);
    if (tid < 128) { bS[tid] = bias[tid]; cS[tid] = ctx[tid]; }

    // stage W hi/lo (row f, stride 272B). 256 thr, 128 rows.
    {
        const int r = tid >> 1;
        const int c0 = (tid & 1) * 64;
#pragma unroll
        for (int i = 0; i < 8; i++) {
            const int c = c0 + i * 8;
            *reinterpret_cast<uint4*>(smem + SM_WH + r * ROWB + c * 2) =
                *reinterpret_cast<const uint4*>(&g_Whi[r * Eq + c]);
            *reinterpret_cast<uint4*>(smem + SM_WL + r * ROWB + c * 2) =
                *reinterpret_cast<const uint4*>(&g_Wlo[r * Eq + c]);
        }
    }

    // per-thread x-load geometry
    const int xr   = tid >> 1;
    const int half = (tid & 1) * 64;

    // warp tile: rows rowG..rowG+31, cols colG..colG+63
    const int rowG = (wid >> 1) * 32;
    const int colG = (wid & 1) * 64;

    // ldmatrix A addresses (per m-block of 16 rows)
    const uint32_t aColB = (lane >> 4) * 16;
    const uint32_t aAddr0H = sb + SM_XH + (uint32_t)(rowG + (lane & 15)) * ROWB + aColB;
    const uint32_t aAddr1H = aAddr0H + 16 * ROWB;
    const uint32_t dXL = (uint32_t)(SM_XL - SM_XH);
    // ldmatrix B addresses (per n-block of 16 cols)
    const int rowB = (lane & 7) + ((lane & 16) >> 1);
    const uint32_t colB = (lane & 8) ? 16u : 0u;
    const uint32_t bBaseH = sb + SM_WH + (uint32_t)(colG + rowB) * ROWB + colB;
    const uint32_t dWL = (uint32_t)(SM_WL - SM_WH);

    float4 st[16];   // staging: 64 floats for next tile

    int tile = blockIdx.x;
    {
        const float* xrow = x + (size_t)(tile * TM + xr) * Eq + half;
#pragma unroll
        for (int i = 0; i < 16; i++) st[i] = reinterpret_cast<const float4*>(xrow)[i];
    }
    __syncthreads(); // W staged
    // convert tile0 into smem
#pragma unroll
    for (int i = 0; i < 8; i++) {
        float fv[8] = {st[2*i].x, st[2*i].y, st[2*i].z, st[2*i].w,
                       st[2*i+1].x, st[2*i+1].y, st[2*i+1].z, st[2*i+1].w};
        float hv[8], lv[8];
#pragma unroll
        for (int j = 0; j < 8; j++) {
            hv[j] = __bfloat162float(__float2bfloat16_rn(fv[j]));
            lv[j] = fv[j] - hv[j];
        }
        uint4 uh, ul;
        uh.x = pack_bf16x2(hv[0], hv[1]); uh.y = pack_bf16x2(hv[2], hv[3]);
        uh.z = pack_bf16x2(hv[4], hv[5]); uh.w = pack_bf16x2(hv[6], hv[7]);
        ul.x = pack_bf16x2(lv[0], lv[1]); ul.y = pack_bf16x2(lv[2], lv[3]);
        ul.z = pack_bf16x2(lv[4], lv[5]); ul.w = pack_bf16x2(lv[6], lv[7]);
        const int c = half + i * 8;
        *reinterpret_cast<uint4*>(smem + SM_XH + xr * ROWB + c * 2) = uh;
        *reinterpret_cast<uint4*>(smem + SM_XL + xr * ROWB + c * 2) = ul;
    }
    __syncthreads();

    while (tile < TILES) {
        const int tbase = tile * TM;
        const int next  = tile + gridDim.x;

        // ---- prefetch next tile into regs (latency hidden by MMA) ----
        if (next < TILES) {
            const float* xrow = x + (size_t)(next * TM + xr) * Eq + half;
#pragma unroll
            for (int i = 0; i < 16; i++) st[i] = reinterpret_cast<const float4*>(xrow)[i];
        }

        // ---- MMA mainloop: d = xh*Wh + xh*Wl + xl*Wh ----
        float d[2][8][4];
#pragma unroll
        for (int mb = 0; mb < 2; mb++)
#pragma unroll
            for (int nb = 0; nb < 8; nb++)
#pragma unroll
                for (int j = 0; j < 4; j++) d[mb][nb][j] = 0.0f;

#pragma unroll
        for (int k = 0; k < 8; k++) {
            const uint32_t ko = (uint32_t)k * 32;
            uint32_t ah[2][4], al[2][4];
            ldsm_x4(aAddr0H + ko,       ah[0][0], ah[0][1], ah[0][2], ah[0][3]);
            ldsm_x4(aAddr0H + dXL + ko, al[0][0], al[0][1], al[0][2], al[0][3]);
            ldsm_x4(aAddr1H + ko,       ah[1][0], ah[1][1], ah[1][2], ah[1][3]);
            ldsm_x4(aAddr1H + dXL + ko, al[1][0], al[1][1], al[1][2], al[1][3]);
#pragma unroll
            for (int nb = 0; nb < 4; nb++) {
                uint32_t bh0, bh1, bh2, bh3, bl0, bl1, bl2, bl3;
                const uint32_t boff = (uint32_t)nb * (16 * ROWB) + ko;
                ldsm_x4(bBaseH + boff,       bh0, bh1, bh2, bh3);
                ldsm_x4(bBaseH + dWL + boff, bl0, bl1, bl2, bl3);
#pragma unroll
                for (int mb = 0; mb < 2; mb++) {
                    mma_bf16(d[mb][nb * 2],     ah[mb][0], ah[mb][1], ah[mb][2], ah[mb][3], bh0, bh1);
                    mma_bf16(d[mb][nb * 2],     ah[mb][0], ah[mb][1], ah[mb][2], ah[mb][3], bl0, bl1);
                    mma_bf16(d[mb][nb * 2],     al[mb][0], al[mb][1], al[mb][2], al[mb][3], bh0, bh1);
                    mma_bf16(d[mb][nb * 2 + 1], ah[mb][0], ah[mb][1], ah[mb][2], ah[mb][3], bh2, bh3);
                    mma_bf16(d[mb][nb * 2 + 1], ah[mb][0], ah[mb][1], ah[mb][2], ah[mb][3], bl2, bl3);
                    mma_bf16(d[mb][nb * 2 + 1], al[mb][0], al[mb][1], al[mb][2], al[mb][3], bh2, bh3);
                }
            }
        }

        // ---- epilogue: per-warp partial of ctx . tanh(z + b) over 64 cols ----
#pragma unroll
        for (int mb = 0; mb < 2; mb++) {
            float p0 = 0.0f, p1 = 0.0f;
#pragma unroll
            for (int nb = 0; nb < 8; nb++) {
                const int n0 = colG + nb * 8 + (lane & 3) * 2;
                const float2 bb = *reinterpret_cast<const float2*>(&bS[n0]);
                const float2 cc = *reinterpret_cast<const float2*>(&cS[n0]);
                p0 = fmaf(fast_tanh(d[mb][nb][0] + bb.x), cc.x, p0);
                p0 = fmaf(fast_tanh(d[mb][nb][1] + bb.y), cc.y, p0);
                p1 = fmaf(fast_tanh(d[mb][nb][2] + bb.x), cc.x, p1);
                p1 = fmaf(fast_tanh(d[mb][nb][3] + bb.y), cc.y, p1);
            }
            p0 += __shfl_xor_sync(0xffffffffu, p0, 1);
            p0 += __shfl_xor_sync(0xffffffffu, p0, 2);
            p1 += __shfl_xor_sync(0xffffffffu, p1, 1);
            p1 += __shfl_xor_sync(0xffffffffu, p1, 2);
            if ((lane & 3) == 0) {
                const int r = rowG + mb * 16 + (lane >> 2);
                pS[r * 2 + (wid & 1)]       = p0;
                pS[(r + 8) * 2 + (wid & 1)] = p1;
            }
        }
        __syncthreads();   // partials visible; all ldsm of this tile complete

        // ---- finalize scores (threads 0..127) ----
        if (tid < 128) {
            const int tok = tbase + tid;
            float s = (pS[tid * 2] + pS[tid * 2 + 1]) * 0.08838834764831845f;
            if (mask[tok] == 0) s = -1e9f;
            g_scores[tok] = s;
            atomicMaxFloat(&g_segmax[(tok / Nq) * IDXq + index[tok]], s);
        }

        // ---- convert staged regs -> smem for next tile ----
        if (next < TILES) {
#pragma unroll
            for (int i = 0; i < 8; i++) {
                float fv[8] = {st[2*i].x, st[2*i].y, st[2*i].z, st[2*i].w,
                               st[2*i+1].x, st[2*i+1].y, st[2*i+1].z, st[2*i+1].w};
                float hv[8], lv[8];
#pragma unroll
                for (int j = 0; j < 8; j++) {
                    hv[j] = __bfloat162float(__float2bfloat16_rn(fv[j]));
                    lv[j] = fv[j] - hv[j];
                }
                uint4 uh, ul;
                uh.x = pack_bf16x2(hv[0], hv[1]); uh.y = pack_bf16x2(hv[2], hv[3]);
                uh.z = pack_bf16x2(hv[4], hv[5]); uh.w = pack_bf16x2(hv[6], hv[7]);
                ul.x = pack_bf16x2(lv[0], lv[1]); ul.y = pack_bf16x2(lv[2], lv[3]);
                ul.z = pack_bf16x2(lv[4], lv[5]); ul.w = pack_bf16x2(lv[6], lv[7]);
                const int c = half + i * 8;
                *reinterpret_cast<uint4*>(smem + SM_XH + xr * ROWB + c * 2) = uh;
                *reinterpret_cast<uint4*>(smem + SM_XL + xr * ROWB + c * 2) = ul;
            }
        }
        __syncthreads();
        tile = next;
    }
}

// ---------------------------------------------------------------------------
// Pass 2: e = exp(score - segmax); segsum += e. 4 tokens/thread, vectorized.
// ---------------------------------------------------------------------------
__global__ void exp_kernel(const int* __restrict__ index) {
    const int t0 = (blockIdx.x * blockDim.x + threadIdx.x) * 4;  // grid exact: TOT/4
    const int b = t0 / Nq;                 // 4 consecutive tokens, same batch
    const int4  idx = *reinterpret_cast<const int4*>(&index[t0]);
    const float4 sc = *reinterpret_cast<const float4*>(&g_scores[t0]);
    const int s0 = b * IDXq + idx.x, s1 = b * IDXq + idx.y;
    const int s2 = b * IDXq + idx.z, s3 = b * IDXq + idx.w;
    float4 e;
    e.x = __expf(sc.x - g_segmax[s0]);
    e.y = __expf(sc.y - g_segmax[s1]);
    e.z = __expf(sc.z - g_segmax[s2]);
    e.w = __expf(sc.w - g_segmax[s3]);
    *reinterpret_cast<float4*>(&g_e[t0]) = e;
    atomicAdd(&g_segsum[s0], e.x);
    atomicAdd(&g_segsum[s1], e.y);
    atomicAdd(&g_segsum[s2], e.z);
    atomicAdd(&g_segsum[s3], e.w);
}

// ---------------------------------------------------------------------------
// Pass 3: w = e/segsum; attn[t] = w; replica[rep][seg] += x_t * w.
// ---------------------------------------------------------------------------
__global__ void __launch_bounds__(256) scatter_kernel(
    const float* __restrict__ x, const int* __restrict__ index,
    float* __restrict__ attn)
{
    const int t = (blockIdx.x * blockDim.x + threadIdx.x) >> 5; // grid exact: TOT warps
    const int lane = threadIdx.x & 31;
    const int b = t / Nq;
    const int seg = b * IDXq + index[t];
    const float w = g_e[t] / g_segsum[seg];
    if (lane == 0) attn[t] = w;

    float4 v = reinterpret_cast<const float4*>(x + (size_t)t * Eq)[lane];
    v.x *= w; v.y *= w; v.z *= w; v.w *= w;
    float* dst = g_part + (size_t)(blockIdx.x & (NREP - 1)) * OUTF
                        + (size_t)seg * Eq + lane * 4;
    asm volatile("red.global.add.v4.f32 [%0], {%1, %2, %3, %4};"
                 :: "l"(dst), "f"(v.x), "f"(v.y), "f"(v.z), "f"(v.w)
                 : "memory");
}

// ---------------------------------------------------------------------------
// Pass 4: out = sum of replicas (fully writes out; no pre-zero needed)
// ---------------------------------------------------------------------------
__global__ void reduce_kernel(float* __restrict__ out) {
    const int i = blockIdx.x * blockDim.x + threadIdx.x;  // grid exact: OUTF/4
    const float4 a = reinterpret_cast<const float4*>(g_part)[i];
    const float4 b = reinterpret_cast<const float4*>(g_part + OUTF)[i];
    const float4 c = reinterpret_cast<const float4*>(g_part + 2 * OUTF)[i];
    const float4 d = reinterpret_cast<const float4*>(g_part + 3 * OUTF)[i];
    float4 r;
    r.x = (a.x + b.x) + (c.x + d.x);
    r.y = (a.y + b.y) + (c.y + d.y);
    r.z = (a.z + b.z) + (c.z + d.z);
    r.w = (a.w + b.w) + (c.w + d.w);
    reinterpret_cast<float4*>(out)[i] = r;
}

// ---------------------------------------------------------------------------
extern "C" void kernel_launch(void* const* d_in, const int* in_sizes, int n_in,
                              void* d_out, int out_size)
{
    const float* x     = (const float*)d_in[0];
    const float* W     = (const float*)d_in[1];
    const float* bias  = (const float*)d_in[2];
    const float* ctx   = (const float*)d_in[3];
    const int*   mask  = (const int*)d_in[4];
    const int*   index = (const int*)d_in[5];

    float* out  = (float*)d_out;        // [B, IDX, E]
    float* attn = out + OUTF;           // [B, N]

    cudaFuncSetAttribute(score_kernel, cudaFuncAttributeMaxDynamicSharedMemorySize, SM_TOTAL);

    wprep_kernel<<<Eq * Eq / 256, 256>>>(W);
    init_kernel<<<NREP * OUTF / 4 / 256, 256>>>();
    score_kernel<<<152, 256, SM_TOTAL>>>(x, bias, ctx, mask, index);
    exp_kernel<<<TOT / 4 / 320, 320>>>(index);
    scatter_kernel<<<TOT / 8, 256>>>(x, index, attn);
    reduce_kernel<<<OUTF / 4 / 256, 256>>>(out);
}

// round 7
// speedup vs baseline: 3.3420x; 1.0988x over previous
#include <cuda_runtime.h>
#include <cuda_bf16.h>
#include <math.h>
#include <stdint.h>

#define Bq   4
#define Nq   200000
#define Eq   128
#define IDXq 2048
#define TOT  (Bq * Nq)        // 800000 tokens
#define SEGS (Bq * IDXq)      // 8192 segments
#define OUTF (SEGS * Eq)      // 1048576 floats in `out` region
#define TM   128              // tokens per tile
#define TILES (TOT / TM)      // 6250 tiles
#define ROWB 272              // padded bf16 smem row stride (128 bf16 + 8 pad)
#define RAWS 528              // padded fp32 raw row stride bytes (132 floats)
#define NREP 4                // scatter atomic replicas

// ---------------- device scratch (no cudaMalloc allowed) -------------------
__device__ float g_scores[TOT];
__device__ float g_e[TOT];
__device__ float g_segmax[SEGS];
__device__ float g_segsum[SEGS];
__device__ __nv_bfloat16 g_Whi[Eq * Eq];
__device__ __nv_bfloat16 g_Wlo[Eq * Eq];
__device__ float g_part[NREP * OUTF];   // 16MB scatter replicas (L2-resident)

// ---------------- helpers ---------------------------------------------------
__device__ __forceinline__ uint32_t smem_u32(const void* p) {
    uint32_t a;
    asm("{ .reg .u64 t; cvta.to.shared.u64 t, %1; cvt.u32.u64 %0, t; }" : "=r"(a) : "l"(p));
    return a;
}
__device__ __forceinline__ uint32_t pack_bf16x2(float a, float b) {
    uint32_t r;
    asm("cvt.rn.bf16x2.f32 %0, %1, %2;" : "=r"(r) : "f"(b), "f"(a));
    return r;
}
__device__ __forceinline__ void cp_async16(uint32_t saddr, const void* gaddr) {
    asm volatile("cp.async.cg.shared.global [%0], [%1], 16;" :: "r"(saddr), "l"(gaddr));
}
__device__ __forceinline__ void ldsm_x4(uint32_t addr, uint32_t& r0, uint32_t& r1,
                                        uint32_t& r2, uint32_t& r3) {
    asm volatile("ldmatrix.sync.aligned.m8n8.x4.shared.b16 {%0,%1,%2,%3}, [%4];"
                 : "=r"(r0), "=r"(r1), "=r"(r2), "=r"(r3) : "r"(addr));
}
__device__ __forceinline__ void mma_bf16(float* d, uint32_t a0, uint32_t a1, uint32_t a2,
                                         uint32_t a3, uint32_t b0, uint32_t b1) {
    asm volatile(
        "mma.sync.aligned.m16n8k16.row.col.f32.bf16.bf16.f32 "
        "{%0,%1,%2,%3}, {%4,%5,%6,%7}, {%8,%9}, {%0,%1,%2,%3};"
        : "+f"(d[0]), "+f"(d[1]), "+f"(d[2]), "+f"(d[3])
        : "r"(a0), "r"(a1), "r"(a2), "r"(a3), "r"(b0), "r"(b1));
}
// tanh(x) = 1 - 2/(exp(2x)+1), via ex2.approx + rcp.approx (~2^-21 max rel err)
__device__ __forceinline__ float fast_tanh(float x) {
    float e, r;
    asm("ex2.approx.f32 %0, %1;" : "=f"(e) : "f"(x * 2.8853900817779268f));
    asm("rcp.approx.f32 %0, %1;" : "=f"(r) : "f"(e + 1.0f));
    return fmaf(-2.0f, r, 1.0f);
}
__device__ __forceinline__ void atomicMaxFloat(float* addr, float value) {
    if (value >= 0.0f) atomicMax((int*)addr, __float_as_int(value));
    else               atomicMin((unsigned int*)addr, __float_as_uint(value));
}

// ---------------------------------------------------------------------------
__global__ void wprep_kernel(const float* __restrict__ W) {
    int i = blockIdx.x * blockDim.x + threadIdx.x; // 16384 exact
    float w = W[i];
    __nv_bfloat16 hi = __float2bfloat16_rn(w);
    g_Whi[i] = hi;
    g_Wlo[i] = __float2bfloat16_rn(w - __bfloat162float(hi));
}

// zero replicas + init segment stats (idempotent across graph replays)
__global__ void init_kernel() {
    int i = blockIdx.x * blockDim.x + threadIdx.x;   // grid covers NREP*OUTF/4
    reinterpret_cast<float4*>(g_part)[i] = make_float4(0.f, 0.f, 0.f, 0.f);
    if (i < SEGS) {
        g_segmax[i] = __int_as_float(0xFF800000); // -inf
        g_segsum[i] = 0.0f;
    }
}

// ---------------------------------------------------------------------------
// Score pass: persistent HMMA bf16x3-split GEMM, cp.async pipelined.
// tile: 128 tokens x 128 features, K=128. 8 warps in 4x2 (rows32 x cols64).
// ---------------------------------------------------------------------------
#define SM_B   0
#define SM_C   512
#define SM_P   1024                     // partial[128][2] floats
#define SM_WH  2048
#define SM_WL  (SM_WH + 128 * ROWB)
#define SM_XH  (SM_WL + 128 * ROWB)
#define SM_XL  (SM_XH + 128 * ROWB)
#define SM_RAW (SM_XL + 128 * ROWB)     // fp32 raw tile, stride 528B
#define SM_TOTAL (SM_RAW + 128 * RAWS)  // 208896

__global__ void __launch_bounds__(256, 1) score_kernel(
    const float* __restrict__ x, const float* __restrict__ bias,
    const float* __restrict__ ctx, const int* __restrict__ mask,
    const int* __restrict__ index)
{
    extern __shared__ char smem[];
    const uint32_t sb = smem_u32(smem);
    const int tid  = threadIdx.x;
    const int wid  = tid >> 5;
    const int lane = tid & 31;

    float* bS = reinterpret_cast<float*>(smem + SM_B);
    float* cS = reinterpret_cast<float*>(smem + SM_C);
    float* pS = reinterpret_cast<float*>(smem + SM_P);
    if (tid < 128) { bS[tid] = bias[tid]; cS[tid] = ctx[tid]; }

    // stage W hi/lo (row f, stride 272B). 256 thr, 128 rows.
    {
        const int r = tid >> 1;
        const int c0 = (tid & 1) * 64;
#pragma unroll
        for (int i = 0; i < 8; i++) {
            const int c = c0 + i * 8;
            *reinterpret_cast<uint4*>(smem + SM_WH + r * ROWB + c * 2) =
                *reinterpret_cast<const uint4*>(&g_Whi[r * Eq + c]);
            *reinterpret_cast<uint4*>(smem + SM_WL + r * ROWB + c * 2) =
                *reinterpret_cast<const uint4*>(&g_Wlo[r * Eq + c]);
        }
    }

    // per-thread x geometry: row xr, cols half..half+63
    const int xr   = tid >> 1;
    const int half = (tid & 1) * 64;
    const uint32_t rawBase = sb + SM_RAW + (uint32_t)xr * RAWS + (uint32_t)half * 4;

    // warp tile: rows rowG..rowG+31, cols colG..colG+63
    const int rowG = (wid >> 1) * 32;
    const int colG = (wid & 1) * 64;

    const uint32_t aColB = (lane >> 4) * 16;
    const uint32_t aAddr0H = sb + SM_XH + (uint32_t)(rowG + (lane & 15)) * ROWB + aColB;
    const uint32_t aAddr1H = aAddr0H + 16 * ROWB;
    const uint32_t dXL = (uint32_t)(SM_XL - SM_XH);
    const int rowB = (lane & 7) + ((lane & 16) >> 1);
    const uint32_t colB = (lane & 8) ? 16u : 0u;
    const uint32_t bBaseH = sb + SM_WH + (uint32_t)(colG + rowB) * ROWB + colB;
    const uint32_t dWL = (uint32_t)(SM_WL - SM_WH);

    // ---- prologue: cp.async tile0 -> raw, convert to hi/lo ----
    int tile = blockIdx.x;
    {
        const float* xrow = x + (size_t)(tile * TM + xr) * Eq + half;
#pragma unroll
        for (int i = 0; i < 16; i++) cp_async16(rawBase + i * 16, xrow + i * 4);
        asm volatile("cp.async.commit_group;" ::: "memory");
        asm volatile("cp.async.wait_group 0;" ::: "memory");
    }
    __syncthreads();
#pragma unroll
    for (int i = 0; i < 8; i++) {
        float4 f0 = *reinterpret_cast<const float4*>(smem + (rawBase - sb) + i * 32);
        float4 f1 = *reinterpret_cast<const float4*>(smem + (rawBase - sb) + i * 32 + 16);
        float fv[8] = {f0.x, f0.y, f0.z, f0.w, f1.x, f1.y, f1.z, f1.w};
        float hv[8], lv[8];
#pragma unroll
        for (int j = 0; j < 8; j++) {
            hv[j] = __bfloat162float(__float2bfloat16_rn(fv[j]));
            lv[j] = fv[j] - hv[j];
        }
        uint4 uh, ul;
        uh.x = pack_bf16x2(hv[0], hv[1]); uh.y = pack_bf16x2(hv[2], hv[3]);
        uh.z = pack_bf16x2(hv[4], hv[5]); uh.w = pack_bf16x2(hv[6], hv[7]);
        ul.x = pack_bf16x2(lv[0], lv[1]); ul.y = pack_bf16x2(lv[2], lv[3]);
        ul.z = pack_bf16x2(lv[4], lv[5]); ul.w = pack_bf16x2(lv[6], lv[7]);
        const int c = half + i * 8;
        *reinterpret_cast<uint4*>(smem + SM_XH + xr * ROWB + c * 2) = uh;
        *reinterpret_cast<uint4*>(smem + SM_XL + xr * ROWB + c * 2) = ul;
    }
    __syncthreads();

    while (tile < TILES) {
        const int tbase = tile * TM;
        const int next  = tile + gridDim.x;

        // ---- issue cp.async for next tile (no registers held) ----
        if (next < TILES) {
            const float* xrow = x + (size_t)(next * TM + xr) * Eq + half;
#pragma unroll
            for (int i = 0; i < 16; i++) cp_async16(rawBase + i * 16, xrow + i * 4);
            asm volatile("cp.async.commit_group;" ::: "memory");
        }

        // ---- MMA mainloop: d = xh*Wh + xh*Wl + xl*Wh ----
        float d[2][8][4];
#pragma unroll
        for (int mb = 0; mb < 2; mb++)
#pragma unroll
            for (int nb = 0; nb < 8; nb++)
#pragma unroll
                for (int j = 0; j < 4; j++) d[mb][nb][j] = 0.0f;

#pragma unroll
        for (int k = 0; k < 8; k++) {
            const uint32_t ko = (uint32_t)k * 32;
            uint32_t ah[2][4], al[2][4];
            ldsm_x4(aAddr0H + ko,       ah[0][0], ah[0][1], ah[0][2], ah[0][3]);
            ldsm_x4(aAddr0H + dXL + ko, al[0][0], al[0][1], al[0][2], al[0][3]);
            ldsm_x4(aAddr1H + ko,       ah[1][0], ah[1][1], ah[1][2], ah[1][3]);
            ldsm_x4(aAddr1H + dXL + ko, al[1][0], al[1][1], al[1][2], al[1][3]);
#pragma unroll
            for (int nb = 0; nb < 4; nb++) {
                uint32_t bh0, bh1, bh2, bh3, bl0, bl1, bl2, bl3;
                const uint32_t boff = (uint32_t)nb * (16 * ROWB) + ko;
                ldsm_x4(bBaseH + boff,       bh0, bh1, bh2, bh3);
                ldsm_x4(bBaseH + dWL + boff, bl0, bl1, bl2, bl3);
#pragma unroll
                for (int mb = 0; mb < 2; mb++) {
                    mma_bf16(d[mb][nb * 2],     ah[mb][0], ah[mb][1], ah[mb][2], ah[mb][3], bh0, bh1);
                    mma_bf16(d[mb][nb * 2],     ah[mb][0], ah[mb][1], ah[mb][2], ah[mb][3], bl0, bl1);
                    mma_bf16(d[mb][nb * 2],     al[mb][0], al[mb][1], al[mb][2], al[mb][3], bh0, bh1);
                    mma_bf16(d[mb][nb * 2 + 1], ah[mb][0], ah[mb][1], ah[mb][2], ah[mb][3], bh2, bh3);
                    mma_bf16(d[mb][nb * 2 + 1], ah[mb][0], ah[mb][1], ah[mb][2], ah[mb][3], bl2, bl3);
                    mma_bf16(d[mb][nb * 2 + 1], al[mb][0], al[mb][1], al[mb][2], al[mb][3], bh2, bh3);
                }
            }
        }

        // ---- epilogue: per-warp partial of ctx . tanh(z + b) over 64 cols ----
#pragma unroll
        for (int mb = 0; mb < 2; mb++) {
            float p0 = 0.0f, p1 = 0.0f;
#pragma unroll
            for (int nb = 0; nb < 8; nb++) {
                const int n0 = colG + nb * 8 + (lane & 3) * 2;
                const float2 bb = *reinterpret_cast<const float2*>(&bS[n0]);
                const float2 cc = *reinterpret_cast<const float2*>(&cS[n0]);
                p0 = fmaf(fast_tanh(d[mb][nb][0] + bb.x), cc.x, p0);
                p0 = fmaf(fast_tanh(d[mb][nb][1] + bb.y), cc.y, p0);
                p1 = fmaf(fast_tanh(d[mb][nb][2] + bb.x), cc.x, p1);
                p1 = fmaf(fast_tanh(d[mb][nb][3] + bb.y), cc.y, p1);
            }
            p0 += __shfl_xor_sync(0xffffffffu, p0, 1);
            p0 += __shfl_xor_sync(0xffffffffu, p0, 2);
            p1 += __shfl_xor_sync(0xffffffffu, p1, 1);
            p1 += __shfl_xor_sync(0xffffffffu, p1, 2);
            if ((lane & 3) == 0) {
                const int r = rowG + mb * 16 + (lane >> 2);
                pS[r * 2 + (wid & 1)]       = p0;
                pS[(r + 8) * 2 + (wid & 1)] = p1;
            }
        }
        asm volatile("cp.async.wait_group 0;" ::: "memory");
        __syncthreads();   // partials visible; ldsm done; raw tile landed

        // ---- finalize scores (threads 0..127) ----
        if (tid < 128) {
            const int tok = tbase + tid;
            float s = (pS[tid * 2] + pS[tid * 2 + 1]) * 0.08838834764831845f;
            if (mask[tok] == 0) s = -1e9f;
            g_scores[tok] = s;
            atomicMaxFloat(&g_segmax[(tok / Nq) * IDXq + index[tok]], s);
        }

        // ---- convert raw -> hi/lo for next tile ----
        if (next < TILES) {
#pragma unroll
            for (int i = 0; i < 8; i++) {
                float4 f0 = *reinterpret_cast<const float4*>(smem + (rawBase - sb) + i * 32);
                float4 f1 = *reinterpret_cast<const float4*>(smem + (rawBase - sb) + i * 32 + 16);
                float fv[8] = {f0.x, f0.y, f0.z, f0.w, f1.x, f1.y, f1.z, f1.w};
                float hv[8], lv[8];
#pragma unroll
                for (int j = 0; j < 8; j++) {
                    hv[j] = __bfloat162float(__float2bfloat16_rn(fv[j]));
                    lv[j] = fv[j] - hv[j];
                }
                uint4 uh, ul;
                uh.x = pack_bf16x2(hv[0], hv[1]); uh.y = pack_bf16x2(hv[2], hv[3]);
                uh.z = pack_bf16x2(hv[4], hv[5]); uh.w = pack_bf16x2(hv[6], hv[7]);
                ul.x = pack_bf16x2(lv[0], lv[1]); ul.y = pack_bf16x2(lv[2], lv[3]);
                ul.z = pack_bf16x2(lv[4], lv[5]); ul.w = pack_bf16x2(lv[6], lv[7]);
                const int c = half + i * 8;
                *reinterpret_cast<uint4*>(smem + SM_XH + xr * ROWB + c * 2) = uh;
                *reinterpret_cast<uint4*>(smem + SM_XL + xr * ROWB + c * 2) = ul;
            }
        }
        __syncthreads();
        tile = next;
    }
}

// ---------------------------------------------------------------------------
// Pass 2: e = exp(score - segmax); segsum += e. 4 tokens/thread, vectorized.
// ---------------------------------------------------------------------------
__global__ void exp_kernel(const int* __restrict__ index) {
    const int t0 = (blockIdx.x * blockDim.x + threadIdx.x) * 4;  // grid exact: TOT/4
    const int b = t0 / Nq;
    const int4  idx = *reinterpret_cast<const int4*>(&index[t0]);
    const float4 sc = *reinterpret_cast<const float4*>(&g_scores[t0]);
    const int s0 = b * IDXq + idx.x, s1 = b * IDXq + idx.y;
    const int s2 = b * IDXq + idx.z, s3 = b * IDXq + idx.w;
    float4 e;
    e.x = __expf(sc.x - g_segmax[s0]);
    e.y = __expf(sc.y - g_segmax[s1]);
    e.z = __expf(sc.z - g_segmax[s2]);
    e.w = __expf(sc.w - g_segmax[s3]);
    *reinterpret_cast<float4*>(&g_e[t0]) = e;
    atomicAdd(&g_segsum[s0], e.x);
    atomicAdd(&g_segsum[s1], e.y);
    atomicAdd(&g_segsum[s2], e.z);
    atomicAdd(&g_segsum[s3], e.w);
}

// ---------------------------------------------------------------------------
// Pass 3: 8 tokens per warp, loads batched for MLP; replica red.v4 scatter.
// ---------------------------------------------------------------------------
__global__ void __launch_bounds__(256) scatter_kernel(
    const float* __restrict__ x, const int* __restrict__ index,
    float* __restrict__ attn)
{
    const int gw   = (blockIdx.x * blockDim.x + threadIdx.x) >> 5; // warp id
    const int lane = threadIdx.x & 31;
    const int t0   = gw * 8;                 // 8 tokens, same batch (Nq % 8 == 0)
    const int b    = t0 / Nq;

    // batched x loads: 8 float4 in flight
    float4 v[8];
#pragma unroll
    for (int i = 0; i < 8; i++)
        v[i] = reinterpret_cast<const float4*>(x + (size_t)(t0 + i) * Eq)[lane];

    // each lane computes w for token t0 + (lane&7); broadcast via shfl
    const int myTok = t0 + (lane & 7);
    const int mySeg = b * IDXq + index[myTok];
    const float myW = g_e[myTok] / g_segsum[mySeg];
    if (lane < 8) attn[myTok] = myW;

    float* repBase = g_part + (size_t)(gw & (NREP - 1)) * OUTF;
#pragma unroll
    for (int i = 0; i < 8; i++) {
        const float w = __shfl_sync(0xffffffffu, myW, i);
        const int seg = __shfl_sync(0xffffffffu, mySeg, i);
        float4 s = v[i];
        s.x *= w; s.y *= w; s.z *= w; s.w *= w;
        float* dst = repBase + (size_t)seg * Eq + lane * 4;
        asm volatile("red.global.add.v4.f32 [%0], {%1, %2, %3, %4};"
                     :: "l"(dst), "f"(s.x), "f"(s.y), "f"(s.z), "f"(s.w)
                     : "memory");
    }
}

// ---------------------------------------------------------------------------
// Pass 4: out = sum of replicas (fully writes out; no pre-zero needed)
// ---------------------------------------------------------------------------
__global__ void reduce_kernel(float* __restrict__ out) {
    const int i = blockIdx.x * blockDim.x + threadIdx.x;  // grid exact: OUTF/4
    const float4 a = reinterpret_cast<const float4*>(g_part)[i];
    const float4 b = reinterpret_cast<const float4*>(g_part + OUTF)[i];
    const float4 c = reinterpret_cast<const float4*>(g_part + 2 * OUTF)[i];
    const float4 d = reinterpret_cast<const float4*>(g_part + 3 * OUTF)[i];
    float4 r;
    r.x = (a.x + b.x) + (c.x + d.x);
    r.y = (a.y + b.y) + (c.y + d.y);
    r.z = (a.z + b.z) + (c.z + d.z);
    r.w = (a.w + b.w) + (c.w + d.w);
    reinterpret_cast<float4*>(out)[i] = r;
}

// ---------------------------------------------------------------------------
extern "C" void kernel_launch(void* const* d_in, const int* in_sizes, int n_in,
                              void* d_out, int out_size)
{
    const float* x     = (const float*)d_in[0];
    const float* W     = (const float*)d_in[1];
    const float* bias  = (const float*)d_in[2];
    const float* ctx   = (const float*)d_in[3];
    const int*   mask  = (const int*)d_in[4];
    const int*   index = (const int*)d_in[5];

    float* out  = (float*)d_out;        // [B, IDX, E]
    float* attn = out + OUTF;           // [B, N]

    cudaFuncSetAttribute(score_kernel, cudaFuncAttributeMaxDynamicSharedMemorySize, SM_TOTAL);

    wprep_kernel<<<Eq * Eq / 256, 256>>>(W);
    init_kernel<<<NREP * OUTF / 4 / 256, 256>>>();
    score_kernel<<<152, 256, SM_TOTAL>>>(x, bias, ctx, mask, index);
    exp_kernel<<<TOT / 4 / 320, 320>>>(index);
    scatter_kernel<<<TOT / 8 / 8, 256>>>(x, index, attn);   // 12500 blocks
    reduce_kernel<<<OUTF / 4 / 256, 256>>>(out);
}